// round 7
// baseline (speedup 1.0000x reference)
#include <cuda_runtime.h>
#include <cuda_bf16.h>

// x[B=2048, C=16, S=2000] fp32.
// Attention branch is identity (softmax rows sum to 1), so:
//   out[b,j,s] = LN_j( sum_c Wp[j,c]*x[b,c,s] + bp[j] ) * gp[j] + hp[j]
//
// R5: all arithmetic in packed f32x2 (FFMA2) via inline PTX — ptxas never emits
// packed FFMA from C++. Halves fma-pipe issue (the real limiter: ~79% busy in
// scalar form; ncu's 39.5% is normalized against the packed peak).
// Weights staged in smem as duplicated (w,w) b64 pairs: one LDS.64 broadcast
// feeds both pair-lanes. Matvec is c-outer so only y[] stays register-live.

#define CN   16
#define SN   2000
#define BN   2048
#define LN_EPS 1e-5f

typedef unsigned long long u64;

__device__ __forceinline__ u64 fma2(u64 a, u64 b, u64 c) {
    u64 d; asm("fma.rn.f32x2 %0, %1, %2, %3;" : "=l"(d) : "l"(a), "l"(b), "l"(c)); return d;
}
__device__ __forceinline__ u64 add2(u64 a, u64 b) {
    u64 d; asm("add.rn.f32x2 %0, %1, %2;" : "=l"(d) : "l"(a), "l"(b)); return d;
}
__device__ __forceinline__ u64 mul2(u64 a, u64 b) {
    u64 d; asm("mul.rn.f32x2 %0, %1, %2;" : "=l"(d) : "l"(a), "l"(b)); return d;
}
__device__ __forceinline__ u64 pack2(float lo, float hi) {
    u64 d; asm("mov.b64 %0, {%1, %2};" : "=l"(d) : "f"(lo), "f"(hi)); return d;
}
__device__ __forceinline__ void unpack2(u64 a, float& lo, float& hi) {
    asm("mov.b64 {%0, %1}, %2;" : "=f"(lo), "=f"(hi) : "l"(a));
}

__global__ __launch_bounds__(256, 2) void fused_proj_ln_p2(
    const float* __restrict__ x,
    const float* __restrict__ Wp,
    const float* __restrict__ bp,
    const float* __restrict__ gp,
    const float* __restrict__ hp,
    float* __restrict__ out)
{
    __shared__ u64 sW2[CN * CN];          // (w,w) duplicated pairs
    __shared__ u64 sb2[CN], sg2[CN], sh2[CN];

    const int t = threadIdx.x;
    if (t < CN * CN) { const float w = Wp[t]; sW2[t] = pack2(w, w); }
    if (t < CN) {
        sb2[t] = pack2(bp[t], bp[t]);
        sg2[t] = pack2(gp[t], gp[t]);
        sh2[t] = pack2(hp[t], hp[t]);
    }
    __syncthreads();

    // One thread handles 4 consecutive s positions (two f32x2 pairs).
    const unsigned GPB = SN / 4;                  // 500
    unsigned g = blockIdx.x * 256u + (unsigned)t;
    if (g >= (unsigned)BN * GPB) return;          // grid sized exactly; guard anyway
    const unsigned b  = g / GPB;
    const unsigned s4 = (g % GPB) * 4u;

    const float* xb = x + (size_t)b * (CN * SN) + s4;

    // y[j] accumulators: lo pair = (s4+0, s4+1), hi pair = (s4+2, s4+3).
    u64 ylo[CN], yhi[CN];
#pragma unroll
    for (int j = 0; j < CN; ++j) { ylo[j] = sb2[j]; yhi[j] = sb2[j]; }

    // c-outer matvec: v[c] loaded (LDG.128, coalesced) and consumed immediately;
    // ptxas pipelines loads ahead within the register budget.
#pragma unroll
    for (int c = 0; c < CN; ++c) {
        const ulonglong2 vc =
            *reinterpret_cast<const ulonglong2*>(xb + (size_t)c * SN);
#pragma unroll
        for (int j = 0; j < CN; ++j) {
            const u64 w = sW2[j * CN + c];        // LDS.64 broadcast
            ylo[j] = fma2(w, vc.x, ylo[j]);
            yhi[j] = fma2(w, vc.y, yhi[j]);
        }
    }

    // mean: negmu = -(1/16) * sum_j y[j]   (per lane)
    u64 slo = ylo[0], shi = yhi[0];
#pragma unroll
    for (int j = 1; j < CN; ++j) { slo = add2(slo, ylo[j]); shi = add2(shi, yhi[j]); }
    const u64 ninv2  = pack2(-1.0f / (float)CN, -1.0f / (float)CN);
    const u64 negmul = mul2(slo, ninv2);
    const u64 negmuh = mul2(shi, ninv2);

    // variance
    u64 vlo = 0ull, vhi = 0ull;
#pragma unroll
    for (int j = 0; j < CN; ++j) {
        const u64 dlo = add2(ylo[j], negmul);
        const u64 dhi = add2(yhi[j], negmuh);
        vlo = fma2(dlo, dlo, vlo);
        vhi = fma2(dhi, dhi, vhi);
    }
    float va, vb, vc_, vd;
    unpack2(vlo, va, vb);
    unpack2(vhi, vc_, vd);
    const float inv = 1.0f / (float)CN;
    const u64 rslo = pack2(rsqrtf(va  * inv + LN_EPS), rsqrtf(vb * inv + LN_EPS));
    const u64 rshi = pack2(rsqrtf(vc_ * inv + LN_EPS), rsqrtf(vd * inv + LN_EPS));

    float* ob = out + (size_t)b * (CN * SN) + s4;
#pragma unroll
    for (int j = 0; j < CN; ++j) {
        const u64 g2 = sg2[j];
        const u64 h2 = sh2[j];
        const u64 dlo = add2(ylo[j], negmul);
        const u64 dhi = add2(yhi[j], negmuh);
        ulonglong2 o;
        o.x = fma2(mul2(dlo, rslo), g2, h2);
        o.y = fma2(mul2(dhi, rshi), g2, h2);
        *reinterpret_cast<ulonglong2*>(ob + (size_t)j * SN) = o;  // STG.128
    }
}

extern "C" void kernel_launch(void* const* d_in, const int* in_sizes, int n_in,
                              void* d_out, int out_size)
{
    // metadata order: x, Wq, bq, gq, hq, Wk, bk, gk, hk, Wp, bp, gp, hp
    const float* x  = (const float*)d_in[0];
    const float* Wp = (const float*)d_in[9];
    const float* bp = (const float*)d_in[10];
    const float* gp = (const float*)d_in[11];
    const float* hp = (const float*)d_in[12];
    float* out = (float*)d_out;

    const unsigned groups = (unsigned)BN * (SN / 4);   // 1,024,000
    const unsigned blocks = (groups + 255u) / 256u;    // 4000
    fused_proj_ln_p2<<<blocks, 256>>>(x, Wp, bp, gp, hp, out);
}

// round 10
// speedup vs baseline: 1.1404x; 1.1404x over previous
#include <cuda_runtime.h>
#include <cuda_bf16.h>

// x[B=2048, C=16, S=2000] fp32.
// Attention branch is identity (softmax rows sum to 1), so:
//   out[b,j,s] = LN_j( sum_c Wp[j,c]*x[b,c,s] + bp[j] ) * gp[j] + hp[j]
//
// R8: R3's front-batched-load structure (the proven MLP source) + packed
// FFMA2 math in two 8-channel phases (v regs reused) + persistent exact-wave
// grid (296 CTAs, grid-stride) + streaming stores.

#define CN   16
#define SN   2000
#define BN   2048
#define LN_EPS 1e-5f

typedef unsigned long long u64;

__device__ __forceinline__ u64 fma2(u64 a, u64 b, u64 c) {
    u64 d; asm("fma.rn.f32x2 %0, %1, %2, %3;" : "=l"(d) : "l"(a), "l"(b), "l"(c)); return d;
}
__device__ __forceinline__ u64 add2(u64 a, u64 b) {
    u64 d; asm("add.rn.f32x2 %0, %1, %2;" : "=l"(d) : "l"(a), "l"(b)); return d;
}
__device__ __forceinline__ u64 mul2(u64 a, u64 b) {
    u64 d; asm("mul.rn.f32x2 %0, %1, %2;" : "=l"(d) : "l"(a), "l"(b)); return d;
}
__device__ __forceinline__ u64 pack2(float lo, float hi) {
    u64 d; asm("mov.b64 %0, {%1, %2};" : "=l"(d) : "f"(lo), "f"(hi)); return d;
}
__device__ __forceinline__ void unpack2(u64 a, float& lo, float& hi) {
    asm("mov.b64 {%0, %1}, %2;" : "=f"(lo), "=f"(hi) : "l"(a));
}
__device__ __forceinline__ void stcs128(float* p, u64 lo, u64 hi) {
    asm volatile("st.global.cs.v2.b64 [%0], {%1, %2};" :: "l"(p), "l"(lo), "l"(hi) : "memory");
}

__global__ __launch_bounds__(256, 2) void fused_proj_ln_r8(
    const float* __restrict__ x,
    const float* __restrict__ Wp,
    const float* __restrict__ bp,
    const float* __restrict__ gp,
    const float* __restrict__ hp,
    float* __restrict__ out)
{
    __shared__ u64 sW2[CN * CN];          // (w,w) duplicated pairs
    __shared__ u64 sb2[CN], sg2[CN], sh2[CN];

    const int t = threadIdx.x;
    if (t < CN * CN) { const float w = Wp[t]; sW2[t] = pack2(w, w); }
    if (t < CN) {
        sb2[t] = pack2(bp[t], bp[t]);
        sg2[t] = pack2(gp[t], gp[t]);
        sh2[t] = pack2(hp[t], hp[t]);
    }
    __syncthreads();

    const unsigned GPB    = SN / 4;                       // 500 groups of 4 s per b
    const unsigned total  = (unsigned)BN * GPB;           // 1,024,000 tiles
    const unsigned stride = gridDim.x * 256u;             // 296*256 = 75,776

    for (unsigned g = blockIdx.x * 256u + (unsigned)t; g < total; g += stride) {
        const unsigned b  = g / GPB;
        const unsigned s4 = (g % GPB) * 4u;

        const float* xb = x + (size_t)b * (CN * SN) + s4;

        // y accumulators: lo pair = s4+0,1 ; hi pair = s4+2,3.
        u64 ylo[CN], yhi[CN];
#pragma unroll
        for (int j = 0; j < CN; ++j) { ylo[j] = sb2[j]; yhi[j] = sb2[j]; }

        // ---- phase A: channels 0..7 front-batched (8x LDG.128) ----
        ulonglong2 v[8];
#pragma unroll
        for (int c = 0; c < 8; ++c)
            v[c] = *reinterpret_cast<const ulonglong2*>(xb + (size_t)c * SN);
#pragma unroll
        for (int j = 0; j < CN; ++j) {
            u64 alo = ylo[j], ahi = yhi[j];
#pragma unroll
            for (int c = 0; c < 8; ++c) {
                const u64 w = sW2[j * CN + c];
                alo = fma2(w, v[c].x, alo);
                ahi = fma2(w, v[c].y, ahi);
            }
            ylo[j] = alo; yhi[j] = ahi;
        }

        // ---- phase B: channels 8..15, reuse v registers ----
#pragma unroll
        for (int c = 0; c < 8; ++c)
            v[c] = *reinterpret_cast<const ulonglong2*>(xb + (size_t)(c + 8) * SN);
#pragma unroll
        for (int j = 0; j < CN; ++j) {
            u64 alo = ylo[j], ahi = yhi[j];
#pragma unroll
            for (int c = 0; c < 8; ++c) {
                const u64 w = sW2[j * CN + c + 8];
                alo = fma2(w, v[c].x, alo);
                ahi = fma2(w, v[c].y, ahi);
            }
            ylo[j] = alo; yhi[j] = ahi;
        }

        // ---- LayerNorm over the 16 channels (packed) ----
        u64 slo = ylo[0], shi = yhi[0];
#pragma unroll
        for (int j = 1; j < CN; ++j) { slo = add2(slo, ylo[j]); shi = add2(shi, yhi[j]); }
        const u64 ninv2  = pack2(-1.0f / (float)CN, -1.0f / (float)CN);
        const u64 negmul = mul2(slo, ninv2);
        const u64 negmuh = mul2(shi, ninv2);

        u64 vlo = 0ull, vhi = 0ull;
#pragma unroll
        for (int j = 0; j < CN; ++j) {
            const u64 dlo = add2(ylo[j], negmul);
            const u64 dhi = add2(yhi[j], negmuh);
            vlo = fma2(dlo, dlo, vlo);
            vhi = fma2(dhi, dhi, vhi);
        }
        float va, vb2, vc2, vd;
        unpack2(vlo, va, vb2);
        unpack2(vhi, vc2, vd);
        const float inv = 1.0f / (float)CN;
        const u64 rslo = pack2(rsqrtf(va  * inv + LN_EPS), rsqrtf(vb2 * inv + LN_EPS));
        const u64 rshi = pack2(rsqrtf(vc2 * inv + LN_EPS), rsqrtf(vd  * inv + LN_EPS));

        float* ob = out + (size_t)b * (CN * SN) + s4;
#pragma unroll
        for (int j = 0; j < CN; ++j) {
            const u64 g2 = sg2[j];
            const u64 h2 = sh2[j];
            const u64 dlo = add2(ylo[j], negmul);
            const u64 dhi = add2(yhi[j], negmuh);
            stcs128(ob + (size_t)j * SN,
                    fma2(mul2(dlo, rslo), g2, h2),
                    fma2(mul2(dhi, rshi), g2, h2));
        }
    }
}

extern "C" void kernel_launch(void* const* d_in, const int* in_sizes, int n_in,
                              void* d_out, int out_size)
{
    // metadata order: x, Wq, bq, gq, hq, Wk, bk, gk, hk, Wp, bp, gp, hp
    const float* x  = (const float*)d_in[0];
    const float* Wp = (const float*)d_in[9];
    const float* bp = (const float*)d_in[10];
    const float* gp = (const float*)d_in[11];
    const float* hp = (const float*)d_in[12];
    float* out = (float*)d_out;

    // Exact two full waves on 148 SMs at 2 CTAs/SM; grid-stride covers the rest.
    fused_proj_ln_r8<<<296, 256>>>(x, Wp, bp, gp, hp, out);
}